// round 17
// baseline (speedup 1.0000x reference)
#include <cuda_runtime.h>
#include <cuda_fp16.h>
#include <math.h>
#include <stdint.h>

// Problem constants (fixed shapes)
#define BB   16
#define IC   128
#define OC   128
#define HH   128
#define WW   128
#define EE   16
#define HWSZ (HH*WW)            // 16384
#define KK   9
#define OIK  (OC*IC*KK)         // 147456

// ---------------- device scratch (static, no runtime alloc) ----------------
__device__ float  g_p  [BB*IC];                 // pooled x
__device__ float  g_rw [BB*EE];                 // routing weights (softmax)
__device__ __half g_wh [(size_t)BB*OIK];        // per-sample weights, fp16 fragment layout (4.7 MB)
__device__ float  g_out[(size_t)BB*OC*HWSZ];    // conv output              (134 MB)
__device__ float  g_cp [BB*OC];                 // per-(b,o) sums for SE
__device__ float  g_cw [BB*OC];                 // SE channel weights
__device__ float  g_mean[BB*HWSZ];              // spatial-attn mean map
__device__ float  g_max [BB*HWSZ];              // spatial-attn max map
__device__ float  g_sw [BB*HWSZ];               // spatial-attn sigmoid map

__device__ __forceinline__ float bn_scale(float g) {
    return g * rsqrtf(1.0f + 1e-5f);
}
__device__ __forceinline__ float sigmoidf_(float v) {
    return 1.0f / (1.0f + __expf(-v));
}

// ---------------- K1: global average pool of x -> g_p ----------------
__global__ void k_pool(const float* __restrict__ x) {
    int b = blockIdx.x >> 7;
    int c = blockIdx.x & 127;
    const float* p = x + ((size_t)b * IC + c) * HWSZ;
    float s = 0.0f;
    for (int i = threadIdx.x; i < HWSZ; i += 256) s += p[i];
    __shared__ float sm[256];
    sm[threadIdx.x] = s;
    __syncthreads();
    for (int st = 128; st > 0; st >>= 1) {
        if (threadIdx.x < st) sm[threadIdx.x] += sm[threadIdx.x + st];
        __syncthreads();
    }
    if (threadIdx.x == 0) g_p[b * IC + c] = sm[0] * (1.0f / HWSZ);
}

// ---------------- K2: routing MLP + softmax (1 block) ----------------
__global__ void k_route(const float* __restrict__ rw1, const float* __restrict__ g1, const float* __restrict__ b1,
                        const float* __restrict__ rw2, const float* __restrict__ g2, const float* __restrict__ b2,
                        const float* __restrict__ rw3, const float* __restrict__ rb3) {
    __shared__ float sp[BB*IC];
    __shared__ float sh[BB*EE];
    __shared__ float sg[BB*IC];
    __shared__ float sl[BB*EE];
    int t = threadIdx.x;
    for (int i = t; i < BB*IC; i += 256) sp[i] = g_p[i];
    for (int i = t; i < BB*OC; i += 256) g_cp[i] = 0.0f;   // zero SE accumulators
    __syncthreads();
    {
        int b = t >> 4, j = t & 15;
        float a = 0.0f;
        for (int i = 0; i < IC; i++) a += sp[b*IC + i] * rw1[j*IC + i];
        a = a * bn_scale(g1[j]) + b1[j];
        sh[t] = fmaxf(a, 0.0f);
    }
    __syncthreads();
    for (int k = 0; k < 8; k++) {
        int idx = t + k*256;
        int b = idx >> 7, i = idx & 127;
        float a = 0.0f;
        for (int j = 0; j < EE; j++) a += sh[b*EE + j] * rw2[i*EE + j];
        a = a * bn_scale(g2[i]) + b2[i];
        sg[idx] = sigmoidf_(a);
    }
    __syncthreads();
    {
        int b = t >> 4, e = t & 15;
        float a = rb3[e];
        for (int i = 0; i < IC; i++) a += sg[b*IC + i] * rw3[e*IC + i];
        sl[t] = a;
    }
    __syncthreads();
    {
        int b = t >> 4;
        float m = -1e30f;
        for (int k = 0; k < EE; k++) m = fmaxf(m, sl[b*EE + k]);
        float s = 0.0f;
        for (int k = 0; k < EE; k++) s += __expf(sl[b*EE + k] - m);
        g_rw[t] = __expf(sl[t] - m) / s;
    }
}

// ---------------- K3: expert-weighted kernel generation (fp16 fragment layout) ----------------
// Per-b half layout: [chunk(4)][tap(9)][kk(2)][m(4)][mf(2)][lane(32)][j(8)]  = OIK halfs.
//   o  = m*32 + mf*16 + g + ((j>>1)&1)*8
//   ic = chunk*32 + kk*16 + ((j>>2)&1)*8 + 2*t + (j&1)
// with g = lane>>2, t = lane&3.
__global__ void k_wgen(const float* __restrict__ experts) {
    __shared__ float srw[BB*EE];
    int tid = threadIdx.x;
    srw[tid] = g_rw[tid];
    __syncthreads();
    int flat = blockIdx.x * 256 + tid;       // 0 .. 147455
    int chunk = flat / 36864;
    int r = flat - chunk * 36864;
    int tap = r >> 12;
    int r2 = r & 4095;
    int kk   = r2 >> 11;
    int m    = (r2 >> 9) & 3;
    int mf   = (r2 >> 8) & 1;
    int lane = (r2 >> 3) & 31;
    int j    = r2 & 7;
    int g = lane >> 2, t = lane & 3;
    int o  = m*32 + mf*16 + g + ((j >> 1) & 1)*8;
    int ic = chunk*32 + kk*16 + ((j >> 2) & 1)*8 + 2*t + (j & 1);

    const float* es = experts + ((size_t)o * IC + ic) * KK + tap;
    float acc[BB];
#pragma unroll
    for (int b2 = 0; b2 < BB; b2++) acc[b2] = 0.0f;
    for (int e = 0; e < EE; e++) {
        float ev = es[(size_t)e * OIK];
#pragma unroll
        for (int b2 = 0; b2 < BB; b2++) acc[b2] += srw[b2*EE + e] * ev;
    }
#pragma unroll
    for (int b2 = 0; b2 < BB; b2++) {
        g_wh[(size_t)b2 * OIK + flat] = __float2half_rn(acc[b2]);
    }
}

// ---------------- K4: per-sample 3x3 conv via mma.sync fp16 implicit GEMM ----------------
// CTA = (b, row h). M=128 (o) x N=128 (px) x K=1152. 8 warps 4(M)x2(N), warp tile 32x64.
// A: per-chunk cp.async gmem->smem (72 KB, fragment layout), inner-loop LDS.128 conflict-free.
// B: half in smem, cell stride 40 halfs; fragments via ldmatrix.m8n8.x4 (conflict-free).
#define XS_ICS 40                      // halfs per (r,c) cell (32 used + 8 pad)
#define XS_CW  130
#define XS_HALFS (3*XS_CW*XS_ICS)      // 15600 halfs = 31200 B
#define A_HALFS  36864                 // per-chunk A block (73728 B)
#define CONV_SMEM ((XS_HALFS + A_HALFS)*2)   // 104928 bytes

#define CPA16(dst, src) asm volatile("cp.async.ca.shared.global [%0], [%1], 16;" :: "r"(dst), "l"(src) : "memory")
#define CPC()           asm volatile("cp.async.commit_group;" ::: "memory")
#define CPW0()          asm volatile("cp.async.wait_group 0;" ::: "memory")

#define MMA_F16(dd, Av, B0, B1) \
    asm volatile("mma.sync.aligned.m16n8k16.row.col.f32.f16.f16.f32 " \
                 "{%0,%1,%2,%3}, {%4,%5,%6,%7}, {%8,%9}, {%0,%1,%2,%3};" \
                 : "+f"((dd)[0]), "+f"((dd)[1]), "+f"((dd)[2]), "+f"((dd)[3]) \
                 : "r"((Av).x), "r"((Av).y), "r"((Av).z), "r"((Av).w), \
                   "r"(B0), "r"(B1))

#define LDMX4(r0, r1, r2, r3, addr) \
    asm volatile("ldmatrix.sync.aligned.m8n8.x4.shared.b16 {%0,%1,%2,%3}, [%4];" \
                 : "=r"(r0), "=r"(r1), "=r"(r2), "=r"(r3) : "r"(addr))

__global__ void __launch_bounds__(256, 2) k_conv_mma(const float* __restrict__ x) {
    extern __shared__ __half xsh[];    // [3 r][130 c][40 ic-halfs] then A block [36864]
    __half* Ash = xsh + XS_HALFS;
    uint32_t a_dst  = (uint32_t)__cvta_generic_to_shared(Ash);
    uint32_t xs_u32 = (uint32_t)__cvta_generic_to_shared(xsh);

    int tid  = threadIdx.x;
    int lane = tid & 31, wid = tid >> 5;
    int g = lane >> 2, t = lane & 3;
    int m4 = wid & 3;
    int om0 = m4 * 32;
    int pn0 = (wid >> 2) * 64;
    int b = blockIdx.x >> 7;
    int h = blockIdx.x & 127;

    const float* xb = x + (size_t)b * IC * HWSZ;
    const __half* wbase = g_wh + (size_t)b * OIK;

    float d[2][8][4];
#pragma unroll
    for (int mf = 0; mf < 2; mf++)
#pragma unroll
        for (int nf = 0; nf < 8; nf++)
#pragma unroll
            for (int r = 0; r < 4; r++) d[mf][nf][r] = 0.0f;

    // per-thread bases
    // ldmatrix row address: lane l -> matrix j=l>>3 (kk=j>>1, kgroup=j&1), row r=l&7 (n offset)
    uint32_t p_lm = xs_u32 +
        (((pn0 + (lane & 7)) * XS_ICS) + ((lane >> 4) * 16) + (((lane >> 3) & 1) * 8)) * 2;
    const __half* awp = Ash + m4 * 512 + lane * 8;              // A fragments (halfs)

    for (int chunk = 0; chunk < 4; chunk++) {
        __syncthreads();               // all warps done reading xsh/Ash
        // ---- kick off A block copy for this chunk (72 KB, linear, coalesced) ----
        {
            const char* asrc = (const char*)(wbase + (size_t)chunk * A_HALFS);
#pragma unroll
            for (int it = 0; it < 18; it++) {
                int off = (it * 256 + tid) * 16;
                CPA16(a_dst + off, asrc + off);
            }
            CPC();
        }
        // ---- stage x rows h-1..h+1 for this 32-ic chunk (fp16, division-free) ----
        const float* xc = xb + (size_t)chunk * 32 * HWSZ;
        for (int pr = wid; pr < 96; pr += 8) {       // pr = r*32 + icc
            int r = pr >> 5, icc = pr & 31;
            int hin = h - 1 + r;
            bool rowok = (unsigned)hin < 128u;
            const float* xr = xc + (size_t)icc * HWSZ + hin * WW;
            __half* drow = xsh + r * (XS_CW * XS_ICS) + icc;
#pragma unroll
            for (int c5 = 0; c5 < 5; c5++) {
                int c = lane + c5 * 32;
                if (c < 130) {
                    int win = c - 1;
                    float v = (rowok && (unsigned)win < 128u) ? xr[win] : 0.0f;
                    drow[c * XS_ICS] = __float2half_rn(v);
                }
            }
        }
        CPW0();
        __syncthreads();

#pragma unroll
        for (int tap = 0; tap < 9; tap++) {
            const int ky = tap / 3, kx = tap - ky * 3;
            // A fragments for this tap: [kk][mf], conflict-free LDS.128 (imm offsets)
            uint4 Af[2][2];
#pragma unroll
            for (int kk = 0; kk < 2; kk++) {
#pragma unroll
                for (int mf = 0; mf < 2; mf++)
                    Af[kk][mf] = *(const uint4*)(awp + tap * 4096 + kk * 2048 + mf * 256);
            }
            uint32_t pt = p_lm + (ky * XS_CW + kx) * (XS_ICS * 2);
#pragma unroll
            for (int nf = 0; nf < 8; nf++) {
                uint32_t b0, b1, b2, b3;
                LDMX4(b0, b1, b2, b3, pt + nf * (8 * XS_ICS * 2));
                MMA_F16(d[0][nf], Af[0][0], b0, b1);
                MMA_F16(d[1][nf], Af[0][1], b0, b1);
                MMA_F16(d[0][nf], Af[1][0], b2, b3);
                MMA_F16(d[1][nf], Af[1][1], b2, b3);
            }
        }
    }

    // ---- epilogue: store + fused SE channel sums ----
    float* ob = g_out + (size_t)b * OC * HWSZ + h * WW;
#pragma unroll
    for (int mf = 0; mf < 2; mf++) {
        int o0 = om0 + mf * 16 + g;
        float s0 = 0.0f, s1 = 0.0f;
#pragma unroll
        for (int nf = 0; nf < 8; nf++) {
            int px = pn0 + nf * 8 + t * 2;
            float2 v0 = make_float2(d[mf][nf][0], d[mf][nf][1]);
            float2 v1 = make_float2(d[mf][nf][2], d[mf][nf][3]);
            *(float2*)(ob + (size_t)o0 * HWSZ + px)       = v0;
            *(float2*)(ob + (size_t)(o0 + 8) * HWSZ + px) = v1;
            s0 += v0.x + v0.y;
            s1 += v1.x + v1.y;
        }
        s0 += __shfl_xor_sync(0xffffffffu, s0, 1);
        s0 += __shfl_xor_sync(0xffffffffu, s0, 2);
        s1 += __shfl_xor_sync(0xffffffffu, s1, 1);
        s1 += __shfl_xor_sync(0xffffffffu, s1, 2);
        if (t == 0) {
            atomicAdd(&g_cp[b * OC + o0], s0);
            atomicAdd(&g_cp[b * OC + o0 + 8], s1);
        }
    }
}

// ---------------- K5: SE channel attention MLP (1 block) ----------------
__global__ void k_chattn(const float* __restrict__ w1, const float* __restrict__ g1, const float* __restrict__ b1,
                         const float* __restrict__ w2, const float* __restrict__ g2, const float* __restrict__ b2) {
    __shared__ float scp[BB*OC];
    __shared__ float sh[BB*16];
    int t = threadIdx.x;
    for (int i = t; i < BB*OC; i += 256) scp[i] = g_cp[i] * (1.0f / HWSZ);
    __syncthreads();
    {
        int b = t >> 4, j = t & 15;
        float a = 0.0f;
        for (int i = 0; i < OC; i++) a += scp[b*OC + i] * w1[j*OC + i];
        a = a * bn_scale(g1[j]) + b1[j];
        sh[t] = fmaxf(a, 0.0f);
    }
    __syncthreads();
    for (int k = 0; k < 8; k++) {
        int idx = t + k*256;
        int b = idx >> 7, i = idx & 127;
        float a = 0.0f;
        for (int j = 0; j < 16; j++) a += sh[b*16 + j] * w2[i*16 + j];
        a = a * bn_scale(g2[i]) + b2[i];
        g_cw[idx] = sigmoidf_(a);
    }
}

// ---------------- K6: spatial mean/max over channels of out*cw ----------------
__global__ void k_spstats() {
    __shared__ float scw[OC];
    int blk = blockIdx.x;
    int b = blk >> 6;
    int t = threadIdx.x;
    if (t < OC) scw[t] = g_cw[b*OC + t];
    __syncthreads();
    int hw = (blk & 63) * 256 + t;
    const float* ob = g_out + (size_t)b * OC * HWSZ + hw;
    float s = 0.0f, m = -1e30f;
    for (int o = 0; o < OC; o++) {
        float v = ob[(size_t)o * HWSZ] * scw[o];
        s += v;
        m = fmaxf(m, v);
    }
    g_mean[b*HWSZ + hw] = s * (1.0f / OC);
    g_max [b*HWSZ + hw] = m;
}

// ---------------- K7: 7x7 spatial-attention conv + sigmoid(bn) ----------------
__global__ void k_spconv(const float* __restrict__ saw, const float* __restrict__ sg, const float* __restrict__ sb) {
    __shared__ float sw_[98];
    int t = threadIdx.x;
    if (t < 98) sw_[t] = saw[t];
    __syncthreads();
    int idx = blockIdx.x * 256 + t;
    int b = idx >> 14;
    int hw = idx & 16383;
    int h = hw >> 7, w = hw & 127;
    float a = 0.0f;
    const float* mb = g_mean + (size_t)b * HWSZ;
    const float* xb = g_max  + (size_t)b * HWSZ;
    for (int kh = 0; kh < 7; kh++) {
        int hh = h + kh - 3;
        if (hh < 0 || hh >= HH) continue;
        for (int kw = 0; kw < 7; kw++) {
            int ww = w + kw - 3;
            if (ww < 0 || ww >= WW) continue;
            int o = hh*WW + ww;
            a += mb[o] * sw_[kh*7 + kw] + xb[o] * sw_[49 + kh*7 + kw];
        }
    }
    a = a * bn_scale(sg[0]) + sb[0];
    g_sw[idx] = sigmoidf_(a);
}

// ---------------- K8: final out = conv*cw*sw + x ----------------
__global__ void k_final(const float* __restrict__ x, float* __restrict__ out) {
    size_t i4 = (size_t)blockIdx.x * 256 + threadIdx.x;
    size_t e = i4 * 4;
    int b  = (int)(e >> 21);
    int o  = (int)((e >> 14) & 127);
    int hw = (int)(e & 16383);
    float cw = g_cw[b*OC + o];
    float4 v  = *(const float4*)(g_out + e);
    float4 xv = ((const float4*)x)[i4];
    float4 sv = *(const float4*)(g_sw + (size_t)b*HWSZ + hw);
    float4 r;
    r.x = v.x * cw * sv.x + xv.x;
    r.y = v.y * cw * sv.y + xv.y;
    r.z = v.z * cw * sv.z + xv.z;
    r.w = v.w * cw * sv.w + xv.w;
    ((float4*)out)[i4] = r;
}

// ---------------- launcher ----------------
extern "C" void kernel_launch(void* const* d_in, const int* in_sizes, int n_in,
                              void* d_out, int out_size) {
    const float* x        = (const float*)d_in[0];
    const float* experts  = (const float*)d_in[1];
    const float* rw1      = (const float*)d_in[2];
    const float* rbn1_g   = (const float*)d_in[3];
    const float* rbn1_b   = (const float*)d_in[4];
    const float* rw2      = (const float*)d_in[5];
    const float* rbn2_g   = (const float*)d_in[6];
    const float* rbn2_b   = (const float*)d_in[7];
    const float* rw3      = (const float*)d_in[8];
    const float* rb3      = (const float*)d_in[9];
    const float* ca_w1    = (const float*)d_in[10];
    const float* ca_bn1_g = (const float*)d_in[11];
    const float* ca_bn1_b = (const float*)d_in[12];
    const float* ca_w2    = (const float*)d_in[13];
    const float* ca_bn2_g = (const float*)d_in[14];
    const float* ca_bn2_b = (const float*)d_in[15];
    const float* sa_w     = (const float*)d_in[16];
    const float* sa_bn_g  = (const float*)d_in[17];
    const float* sa_bn_b  = (const float*)d_in[18];
    float* out = (float*)d_out;

    cudaFuncSetAttribute(k_conv_mma, cudaFuncAttributeMaxDynamicSharedMemorySize, CONV_SMEM);

    k_pool<<<BB*IC, 256>>>(x);
    k_route<<<1, 256>>>(rw1, rbn1_g, rbn1_b, rw2, rbn2_g, rbn2_b, rw3, rb3);
    k_wgen<<<OIK/256, 256>>>(experts);
    k_conv_mma<<<BB*HH, 256, CONV_SMEM>>>(x);
    k_chattn<<<1, 256>>>(ca_w1, ca_bn1_g, ca_bn1_b, ca_w2, ca_bn2_g, ca_bn2_b);
    k_spstats<<<BB*64, 256>>>();
    k_spconv<<<BB*64, 256>>>(sa_w, sa_bn_g, sa_bn_b);
    k_final<<<(BB*OC*HWSZ)/(4*256), 256>>>(x, out);
}